// round 8
// baseline (speedup 1.0000x reference)
#include <cuda_runtime.h>
#include <cuda_bf16.h>
#include <mma.h>
#include <cstdint>

using namespace nvcuda;

#define N_NODES 10000
#define N_EDGES 163840
#define IN_SIZE 512
#define H_SIZE 512
#define OUT_SIZE 64
#define M_PAD 10112   // padded row count (>= ceil(10000/128)*128)

// ---------------- scratch (device globals; no allocation allowed) ----------
// NOTE: g_cnt starts zero (static zero-init) and k_scan re-zeros it after
// consuming it, so it is always zero when k_hist runs (every graph replay).
__device__ float g_dinv[N_NODES];
__device__ int   g_cnt[N_NODES];
__device__ int   g_rowptr[N_NODES + 1];
__device__ int   g_cursor[N_NODES];
__device__ int   g_csrc[N_EDGES];
__device__ float g_w1c[IN_SIZE * H_SIZE];        // W1 RN-rounded to tf32
__device__ float g_w2c[H_SIZE * OUT_SIZE];       // W2 RN-rounded to tf32
__device__ float g_h1[(size_t)M_PAD * H_SIZE];   // x@W1 (raw fp32 accum)
__device__ float g_y[(size_t)M_PAD * H_SIZE];    // relu(Â h1 + b1), tf32-rounded
__device__ float g_h2[(size_t)M_PAD * OUT_SIZE]; // y@W2 (raw fp32 accum)

// ---------------- cp.async helpers ------------------------------------------
__device__ __forceinline__ void cp_async16(void* smem, const void* gmem, int src_size) {
    uint32_t s = (uint32_t)__cvta_generic_to_shared(smem);
    asm volatile("cp.async.cg.shared.global [%0], [%1], 16, %2;"
                 :: "r"(s), "l"(gmem), "r"(src_size));
}
__device__ __forceinline__ void cp_commit() {
    asm volatile("cp.async.commit_group;");
}
template <int N>
__device__ __forceinline__ void cp_wait() {
    asm volatile("cp.async.wait_group %0;" :: "n"(N));
}

// ---------------- weight pre-rounding: W1 and W2 in one launch --------------
__global__ void k_cvt2(const float* __restrict__ W1, float* __restrict__ w1c,
                       const float* __restrict__ W2, float* __restrict__ w2c) {
    const int n1 = IN_SIZE * H_SIZE / 4;   // 65536 float4
    const int n2 = H_SIZE * OUT_SIZE / 4;  // 8192  float4
    int i = blockIdx.x * blockDim.x + threadIdx.x;
    if (i < n1) {
        float4 v = reinterpret_cast<const float4*>(W1)[i];
        v.x = wmma::__float_to_tf32(v.x);
        v.y = wmma::__float_to_tf32(v.y);
        v.z = wmma::__float_to_tf32(v.z);
        v.w = wmma::__float_to_tf32(v.w);
        reinterpret_cast<float4*>(w1c)[i] = v;
    } else if (i < n1 + n2) {
        int j = i - n1;
        float4 v = reinterpret_cast<const float4*>(W2)[j];
        v.x = wmma::__float_to_tf32(v.x);
        v.y = wmma::__float_to_tf32(v.y);
        v.z = wmma::__float_to_tf32(v.z);
        v.w = wmma::__float_to_tf32(v.w);
        reinterpret_cast<float4*>(w2c)[j] = v;
    }
}

// ---------------- CSR build -------------------------------------------------
__global__ void k_hist(const int* __restrict__ dst, int* cnt) {
    int e = blockIdx.x * blockDim.x + threadIdx.x;
    if (e < N_EDGES) atomicAdd(&cnt[dst[e]], 1);
}

// single-block scan (warp-shuffle based, 2 barriers) over 10000 counts.
// Produces rowptr (exclusive), cursor copy, dinv; re-zeros cnt for next replay.
#define SCAN_T 1024
#define SCAN_E 10
__global__ __launch_bounds__(SCAN_T)
void k_scan(int* cnt, int* rowptr, int* cursor, float* dinv) {
    __shared__ int wsum[32];
    const int t = threadIdx.x;
    const int lane = t & 31;
    const int wid = t >> 5;
    const int base = t * SCAN_E;

    int c[SCAN_E];
    int s = 0;
#pragma unroll
    for (int i = 0; i < SCAN_E; i++) {
        int idx = base + i;
        c[i] = (idx < N_NODES) ? cnt[idx] : 0;
        s += c[i];
    }
    // warp-level inclusive scan of per-thread sums
    int ws = s;
#pragma unroll
    for (int o = 1; o < 32; o <<= 1) {
        int v = __shfl_up_sync(0xffffffffu, ws, o);
        if (lane >= o) ws += v;
    }
    if (lane == 31) wsum[wid] = ws;
    __syncthreads();
    if (wid == 0) {
        int v = wsum[lane];
#pragma unroll
        for (int o = 1; o < 32; o <<= 1) {
            int u = __shfl_up_sync(0xffffffffu, v, o);
            if (lane >= o) v += u;
        }
        wsum[lane] = v;
    }
    __syncthreads();

    int warp_excl = (wid == 0) ? 0 : wsum[wid - 1];
    int run = warp_excl + ws - s;  // exclusive prefix for this thread's block
#pragma unroll
    for (int i = 0; i < SCAN_E; i++) {
        int idx = base + i;
        if (idx < N_NODES) {
            rowptr[idx] = run;
            cursor[idx] = run;
            dinv[idx] = rsqrtf((float)(c[i] + 1));  // +1 self loop
            cnt[idx] = 0;                            // re-zero for next replay
            run += c[i];
        }
    }
    if (t == SCAN_T - 1) rowptr[N_NODES] = wsum[31];
}

__global__ void k_fill(const int* __restrict__ src, const int* __restrict__ dst,
                       int* cursor, int* csrc) {
    int e = blockIdx.x * blockDim.x + threadIdx.x;
    if (e >= N_EDGES) return;
    int d = dst[e];
    int pos = atomicAdd(&cursor[d], 1);
    csrc[pos] = src[e];
}

// ---------------- TF32 WMMA GEMM (2-stage cp.async pipeline) ----------------
// CONV_A: round A fragments to tf32 (RN) in registers. B must be pre-rounded.
// C[M_pad,N] = A[M,K] @ B[K,N]; C row stores unguarded (rows padded),
// A rows >= M are zero-filled via cp.async src_size=0.
template <int BM, int BN, int BK, int WM, int WN, bool CONV_A>
__global__ __launch_bounds__(256)
void k_wmma(const float* __restrict__ A, const float* __restrict__ B,
            float* __restrict__ C, int M, int N, int K) {
    constexpr int LDA = BK + 4;
    constexpr int LDB = BN + 4;
    constexpr int WTM = BM / WM;
    constexpr int WTN = BN / WN;
    constexpr int FM = WTM / 16;
    constexpr int FN = WTN / 16;
    __shared__ float As[2][BM * LDA];
    __shared__ float Bs[2][BK * LDB];

    const int tid = threadIdx.x;
    const int wid = tid >> 5;
    const int wm = wid % WM;
    const int wn = wid / WM;
    const int bm = blockIdx.x * BM;
    const int bn = blockIdx.y * BN;

    wmma::fragment<wmma::accumulator, 16, 16, 8, float> acc[FM][FN];
#pragma unroll
    for (int fm = 0; fm < FM; fm++)
#pragma unroll
        for (int fn = 0; fn < FN; fn++) wmma::fill_fragment(acc[fm][fn], 0.0f);

    constexpr int LA = (BM * BK) / (4 * 256);  // float4 chunks of A per thread
    constexpr int LB = (BK * BN) / (4 * 256);  // float4 chunks of B per thread

    auto load_stage = [&](int stg, int k0) {
#pragma unroll
        for (int i = 0; i < LA; i++) {
            int idx = tid + i * 256;
            int row = idx / (BK / 4);
            int c4 = (idx % (BK / 4)) * 4;
            int gr = bm + row;
            int sz = (gr < M) ? 16 : 0;
            if (gr >= M) gr = M - 1;  // keep address in-bounds; sz=0 zero-fills
            cp_async16(&As[stg][row * LDA + c4],
                       &A[(size_t)gr * K + k0 + c4], sz);
        }
#pragma unroll
        for (int i = 0; i < LB; i++) {
            int idx = tid + i * 256;
            int kr = idx / (BN / 4);
            int c4 = (idx % (BN / 4)) * 4;
            cp_async16(&Bs[stg][kr * LDB + c4],
                       &B[(size_t)(k0 + kr) * N + bn + c4], 16);
        }
        cp_commit();
    };

    const int S = K / BK;
    load_stage(0, 0);

    for (int s = 0; s < S; s++) {
        int buf = s & 1;
        if (s + 1 < S) {
            load_stage(buf ^ 1, (s + 1) * BK);
            cp_wait<1>();
        } else {
            cp_wait<0>();
        }
        __syncthreads();

#pragma unroll
        for (int kk = 0; kk < BK; kk += 8) {
            wmma::fragment<wmma::matrix_a, 16, 16, 8, wmma::precision::tf32, wmma::row_major> af[FM];
            wmma::fragment<wmma::matrix_b, 16, 16, 8, wmma::precision::tf32, wmma::row_major> bf[FN];
#pragma unroll
            for (int fm = 0; fm < FM; fm++) {
                wmma::load_matrix_sync(af[fm], &As[buf][(wm * WTM + fm * 16) * LDA + kk], LDA);
                if (CONV_A) {
#pragma unroll
                    for (int i = 0; i < af[fm].num_elements; i++)
                        af[fm].x[i] = wmma::__float_to_tf32(af[fm].x[i]);
                }
            }
#pragma unroll
            for (int fn = 0; fn < FN; fn++)
                wmma::load_matrix_sync(bf[fn], &Bs[buf][kk * LDB + wn * WTN + fn * 16], LDB);
#pragma unroll
            for (int fm = 0; fm < FM; fm++)
#pragma unroll
                for (int fn = 0; fn < FN; fn++)
                    wmma::mma_sync(acc[fm][fn], af[fm], bf[fn], acc[fm][fn]);
        }
        __syncthreads();
    }

#pragma unroll
    for (int fm = 0; fm < FM; fm++)
#pragma unroll
        for (int fn = 0; fn < FN; fn++)
            wmma::store_matrix_sync(
                &C[(size_t)(bm + wm * WTM + fm * 16) * N + bn + wn * WTN + fn * 16],
                acc[fm][fn], N, wmma::mem_row_major);
}

// ---------------- layer-1 aggregate (CSR gather) + self + bias + relu -------
// Output y is RN-rounded to tf32 so GEMM2 needs no in-loop conversion.
__global__ __launch_bounds__(256)
void k_agg1(const int* __restrict__ rowptr, const int* __restrict__ csrc,
            const float* __restrict__ dinv, const float* __restrict__ h1,
            const float* __restrict__ b1, float* __restrict__ y) {
    int node = (blockIdx.x * blockDim.x + threadIdx.x) >> 5;
    if (node >= N_NODES) return;
    int lane = threadIdx.x & 31;
    int beg = __ldg(&rowptr[node]);
    int end = __ldg(&rowptr[node + 1]);
    float dd = __ldg(&dinv[node]);

    float4 a0 = {0, 0, 0, 0}, a1 = {0, 0, 0, 0}, a2 = {0, 0, 0, 0}, a3 = {0, 0, 0, 0};
    const float4* H = reinterpret_cast<const float4*>(h1);

    int j = beg;
    for (; j + 1 < end; j += 2) {
        int s0 = __ldg(&csrc[j]);
        int s1 = __ldg(&csrc[j + 1]);
        float n0 = dd * __ldg(&dinv[s0]);
        float n1 = dd * __ldg(&dinv[s1]);
        const float4* p0 = H + (size_t)s0 * 128;
        const float4* p1 = H + (size_t)s1 * 128;
        float4 u0 = __ldg(p0 + lane);
        float4 u1 = __ldg(p0 + lane + 32);
        float4 u2 = __ldg(p0 + lane + 64);
        float4 u3 = __ldg(p0 + lane + 96);
        float4 w0 = __ldg(p1 + lane);
        float4 w1 = __ldg(p1 + lane + 32);
        float4 w2 = __ldg(p1 + lane + 64);
        float4 w3 = __ldg(p1 + lane + 96);
        a0.x += u0.x * n0 + w0.x * n1; a0.y += u0.y * n0 + w0.y * n1;
        a0.z += u0.z * n0 + w0.z * n1; a0.w += u0.w * n0 + w0.w * n1;
        a1.x += u1.x * n0 + w1.x * n1; a1.y += u1.y * n0 + w1.y * n1;
        a1.z += u1.z * n0 + w1.z * n1; a1.w += u1.w * n0 + w1.w * n1;
        a2.x += u2.x * n0 + w2.x * n1; a2.y += u2.y * n0 + w2.y * n1;
        a2.z += u2.z * n0 + w2.z * n1; a2.w += u2.w * n0 + w2.w * n1;
        a3.x += u3.x * n0 + w3.x * n1; a3.y += u3.y * n0 + w3.y * n1;
        a3.z += u3.z * n0 + w3.z * n1; a3.w += u3.w * n0 + w3.w * n1;
    }
    if (j < end) {
        int s0 = __ldg(&csrc[j]);
        float n0 = dd * __ldg(&dinv[s0]);
        const float4* p0 = H + (size_t)s0 * 128;
        float4 u0 = __ldg(p0 + lane);
        float4 u1 = __ldg(p0 + lane + 32);
        float4 u2 = __ldg(p0 + lane + 64);
        float4 u3 = __ldg(p0 + lane + 96);
        a0.x += u0.x * n0; a0.y += u0.y * n0; a0.z += u0.z * n0; a0.w += u0.w * n0;
        a1.x += u1.x * n0; a1.y += u1.y * n0; a1.z += u1.z * n0; a1.w += u1.w * n0;
        a2.x += u2.x * n0; a2.y += u2.y * n0; a2.z += u2.z * n0; a2.w += u2.w * n0;
        a3.x += u3.x * n0; a3.y += u3.y * n0; a3.z += u3.z * n0; a3.w += u3.w * n0;
    }

    float w = dd * dd;
    const float4* hs = H + (size_t)node * 128;
    const float4* B4 = reinterpret_cast<const float4*>(b1);
    float4* Y = reinterpret_cast<float4*>(y) + (size_t)node * 128;
    float4 accs[4] = {a0, a1, a2, a3};
#pragma unroll
    for (int kchunk = 0; kchunk < 4; kchunk++) {
        int off = lane + kchunk * 32;
        float4 h = __ldg(hs + off);
        float4 b = __ldg(B4 + off);
        float4 r;
        r.x = wmma::__float_to_tf32(fmaxf(accs[kchunk].x + h.x * w + b.x, 0.f));
        r.y = wmma::__float_to_tf32(fmaxf(accs[kchunk].y + h.y * w + b.y, 0.f));
        r.z = wmma::__float_to_tf32(fmaxf(accs[kchunk].z + h.z * w + b.z, 0.f));
        r.w = wmma::__float_to_tf32(fmaxf(accs[kchunk].w + h.w * w + b.w, 0.f));
        Y[off] = r;
    }
}

// ---------------- layer-2 aggregate + self + bias + log_softmax -> out ------
__global__ __launch_bounds__(256)
void k_agg2(const int* __restrict__ rowptr, const int* __restrict__ csrc,
            const float* __restrict__ dinv, const float* __restrict__ h2,
            const float* __restrict__ b2, float* __restrict__ out) {
    int node = (blockIdx.x * blockDim.x + threadIdx.x) >> 5;
    if (node >= N_NODES) return;
    int lane = threadIdx.x & 31;
    int beg = __ldg(&rowptr[node]);
    int end = __ldg(&rowptr[node + 1]);
    float dd = __ldg(&dinv[node]);

    float2 acc = {0, 0};
    const float2* H2 = reinterpret_cast<const float2*>(h2);
    int j = beg;
    for (; j + 1 < end; j += 2) {
        int s0 = __ldg(&csrc[j]);
        int s1 = __ldg(&csrc[j + 1]);
        float n0 = dd * __ldg(&dinv[s0]);
        float n1 = dd * __ldg(&dinv[s1]);
        float2 v0 = __ldg(H2 + (size_t)s0 * 32 + lane);
        float2 v1 = __ldg(H2 + (size_t)s1 * 32 + lane);
        acc.x += v0.x * n0 + v1.x * n1;
        acc.y += v0.y * n0 + v1.y * n1;
    }
    if (j < end) {
        int s0 = __ldg(&csrc[j]);
        float n0 = dd * __ldg(&dinv[s0]);
        float2 v0 = __ldg(H2 + (size_t)s0 * 32 + lane);
        acc.x += v0.x * n0;
        acc.y += v0.y * n0;
    }

    float w = dd * dd;
    float2 hv = __ldg(H2 + (size_t)node * 32 + lane);
    float2 bv = reinterpret_cast<const float2*>(b2)[lane];
    float v0 = acc.x + hv.x * w + bv.x;
    float v1 = acc.y + hv.y * w + bv.y;

    size_t base = (size_t)node * OUT_SIZE;
    out[base + 2 * lane] = v0;
    out[base + 2 * lane + 1] = v1;

    float m = fmaxf(v0, v1);
#pragma unroll
    for (int o = 16; o > 0; o >>= 1) m = fmaxf(m, __shfl_xor_sync(0xffffffffu, m, o));
    float s = expf(v0 - m) + expf(v1 - m);
#pragma unroll
    for (int o = 16; o > 0; o >>= 1) s += __shfl_xor_sync(0xffffffffu, s, o);
    float lse = m + logf(s);
    const size_t half = (size_t)N_NODES * OUT_SIZE;
    out[half + base + 2 * lane] = v0 - lse;
    out[half + base + 2 * lane + 1] = v1 - lse;
}

// ---------------- launch ----------------------------------------------------
extern "C" void kernel_launch(void* const* d_in, const int* in_sizes, int n_in,
                              void* d_out, int out_size) {
    const float* x  = (const float*)d_in[0];
    const int*   ei = (const int*)d_in[1];   // [2, E]: src row then dst row
    const float* W1 = (const float*)d_in[2];
    const float* b1 = (const float*)d_in[3];
    const float* W2 = (const float*)d_in[4];
    const float* b2 = (const float*)d_in[5];
    float* out = (float*)d_out;

    const int* src = ei;
    const int* dst = ei + N_EDGES;

    float *dinv, *w1c, *w2c, *h1, *y, *h2;
    int *cnt, *rowptr, *cursor, *csrc;
    cudaGetSymbolAddress((void**)&dinv,   g_dinv);
    cudaGetSymbolAddress((void**)&cnt,    g_cnt);
    cudaGetSymbolAddress((void**)&rowptr, g_rowptr);
    cudaGetSymbolAddress((void**)&cursor, g_cursor);
    cudaGetSymbolAddress((void**)&csrc,   g_csrc);
    cudaGetSymbolAddress((void**)&w1c,    g_w1c);
    cudaGetSymbolAddress((void**)&w2c,    g_w2c);
    cudaGetSymbolAddress((void**)&h1,     g_h1);
    cudaGetSymbolAddress((void**)&y,      g_y);
    cudaGetSymbolAddress((void**)&h2,     g_h2);

    // 1) round W1 + W2 to tf32 (one launch, region-split grid)
    {
        int total = IN_SIZE * H_SIZE / 4 + H_SIZE * OUT_SIZE / 4;
        k_cvt2<<<(total + 255) / 256, 256>>>(W1, w1c, W2, w2c);
    }
    // 2) histogram (cnt is guaranteed zero: static init / re-zeroed by k_scan)
    k_hist<<<(N_EDGES + 255) / 256, 256>>>(dst, cnt);
    // 3) scan -> rowptr/cursor/dinv (+ re-zero cnt)
    k_scan<<<1, SCAN_T>>>(cnt, rowptr, cursor, dinv);
    // 4) fill CSR column indices
    k_fill<<<(N_EDGES + 255) / 256, 256>>>(src, dst, cursor, csrc);

    // 5) GEMM1: h1 = x @ W1
    {
        dim3 grid((N_NODES + 127) / 128, H_SIZE / 64);
        k_wmma<128, 64, 32, 4, 2, true><<<grid, 256>>>(x, w1c, h1, N_NODES, H_SIZE, IN_SIZE);
    }

    // 6) layer-1 aggregation + relu (profiled launch this round)
    k_agg1<<<(N_NODES * 32 + 255) / 256, 256>>>(rowptr, csrc, dinv, h1, b1, y);

    // 7) GEMM2: h2 = y @ W2 (no conversion anywhere; full wave)
    {
        dim3 grid((N_NODES + 63) / 64, OUT_SIZE / 64);
        k_wmma<64, 64, 32, 4, 2, false><<<grid, 256>>>(y, w2c, h2, N_NODES, OUT_SIZE, H_SIZE);
    }

    // 8) layer-2 aggregation + bias + log_softmax -> out
    k_agg2<<<(N_NODES * 32 + 255) / 256, 256>>>(rowptr, csrc, dinv, h2, b2, out);
}

// round 9
// speedup vs baseline: 1.0073x; 1.0073x over previous
#include <cuda_runtime.h>
#include <cuda_bf16.h>
#include <mma.h>
#include <cstdint>

using namespace nvcuda;

#define N_NODES 10000
#define N_EDGES 163840
#define IN_SIZE 512
#define H_SIZE 512
#define OUT_SIZE 64
#define M_PAD 10112   // padded row count (>= ceil(10000/128)*128)

// ---------------- scratch (device globals; no allocation allowed) ----------
// g_cnt starts zero (static zero-init); k_scan re-zeros it after consuming,
// so it is zero before k_hist on every graph replay.
__device__ float g_dinv[N_NODES];
__device__ int   g_cnt[N_NODES];
__device__ int   g_rowptr[N_NODES + 1];
__device__ int   g_cursor[N_NODES];
__device__ int   g_csrc[N_EDGES];
__device__ float g_h1[(size_t)M_PAD * H_SIZE];   // x@W1 (raw)
__device__ float g_y[(size_t)M_PAD * H_SIZE];    // relu(Â h1 + b1)
__device__ float g_h2[(size_t)M_PAD * OUT_SIZE]; // y@W2 (raw)

// ---------------- CSR build -------------------------------------------------
__global__ void k_hist(const int* __restrict__ dst, int* cnt) {
    int e = blockIdx.x * blockDim.x + threadIdx.x;
    if (e < N_EDGES) atomicAdd(&cnt[dst[e]], 1);
}

// single-block scan (warp-shuffle, 2 barriers) over 10000 counts.
// Produces rowptr (exclusive), cursor copy, dinv; re-zeros cnt for next replay.
#define SCAN_T 1024
#define SCAN_E 10
__global__ __launch_bounds__(SCAN_T)
void k_scan(int* cnt, int* rowptr, int* cursor, float* dinv) {
    __shared__ int wsum[32];
    const int t = threadIdx.x;
    const int lane = t & 31;
    const int wid = t >> 5;
    const int base = t * SCAN_E;

    int c[SCAN_E];
    int s = 0;
#pragma unroll
    for (int i = 0; i < SCAN_E; i++) {
        int idx = base + i;
        c[i] = (idx < N_NODES) ? cnt[idx] : 0;
        s += c[i];
    }
    int ws = s;
#pragma unroll
    for (int o = 1; o < 32; o <<= 1) {
        int v = __shfl_up_sync(0xffffffffu, ws, o);
        if (lane >= o) ws += v;
    }
    if (lane == 31) wsum[wid] = ws;
    __syncthreads();
    if (wid == 0) {
        int v = wsum[lane];
#pragma unroll
        for (int o = 1; o < 32; o <<= 1) {
            int u = __shfl_up_sync(0xffffffffu, v, o);
            if (lane >= o) v += u;
        }
        wsum[lane] = v;
    }
    __syncthreads();

    int warp_excl = (wid == 0) ? 0 : wsum[wid - 1];
    int run = warp_excl + ws - s;
#pragma unroll
    for (int i = 0; i < SCAN_E; i++) {
        int idx = base + i;
        if (idx < N_NODES) {
            rowptr[idx] = run;
            cursor[idx] = run;
            dinv[idx] = rsqrtf((float)(c[i] + 1));  // +1 self loop
            cnt[idx] = 0;                            // re-zero for next replay
            run += c[i];
        }
    }
    if (t == SCAN_T - 1) rowptr[N_NODES] = wsum[31];
}

__global__ void k_fill(const int* __restrict__ src, const int* __restrict__ dst,
                       int* cursor, int* csrc) {
    int e = blockIdx.x * blockDim.x + threadIdx.x;
    if (e >= N_EDGES) return;
    int d = dst[e];
    int pos = atomicAdd(&cursor[d], 1);
    csrc[pos] = src[e];
}

// ---------------- TF32 WMMA GEMM (R3 design: sync loads, single buffer) -----
// fp32->tf32 RN conversion happens in the smem fill path.
// C rows are padded (stores unguarded); A rows >= M read as zero.
template <int BM, int BN, int BK, int WM, int WN>
__global__ __launch_bounds__(256)
void k_wmma(const float* __restrict__ A, const float* __restrict__ B,
            float* __restrict__ C, int M, int N, int K) {
    constexpr int LDA = BK + 4;
    constexpr int LDB = BN + 4;
    constexpr int WTM = BM / WM;
    constexpr int WTN = BN / WN;
    constexpr int FM = WTM / 16;
    constexpr int FN = WTN / 16;
    __shared__ float As[BM * LDA];
    __shared__ float Bs[BK * LDB];

    const int tid = threadIdx.x;
    const int wid = tid >> 5;
    const int wm = wid % WM;
    const int wn = wid / WM;
    const int bm = blockIdx.x * BM;
    const int bn = blockIdx.y * BN;

    wmma::fragment<wmma::accumulator, 16, 16, 8, float> acc[FM][FN];
#pragma unroll
    for (int fm = 0; fm < FM; fm++)
#pragma unroll
        for (int fn = 0; fn < FN; fn++) wmma::fill_fragment(acc[fm][fn], 0.0f);

    constexpr int LA = (BM * BK) / (4 * 256);
    constexpr int LB = (BK * BN) / (4 * 256);

    for (int k0 = 0; k0 < K; k0 += BK) {
#pragma unroll
        for (int i = 0; i < LA; i++) {
            int idx = tid + i * 256;
            int row = idx / (BK / 4);
            int c4 = (idx % (BK / 4)) * 4;
            float4 v = make_float4(0.f, 0.f, 0.f, 0.f);
            if (bm + row < M)
                v = *reinterpret_cast<const float4*>(&A[(size_t)(bm + row) * K + k0 + c4]);
            As[row * LDA + c4 + 0] = wmma::__float_to_tf32(v.x);
            As[row * LDA + c4 + 1] = wmma::__float_to_tf32(v.y);
            As[row * LDA + c4 + 2] = wmma::__float_to_tf32(v.z);
            As[row * LDA + c4 + 3] = wmma::__float_to_tf32(v.w);
        }
#pragma unroll
        for (int i = 0; i < LB; i++) {
            int idx = tid + i * 256;
            int kr = idx / (BN / 4);
            int c4 = (idx % (BN / 4)) * 4;
            float4 v = *reinterpret_cast<const float4*>(&B[(size_t)(k0 + kr) * N + bn + c4]);
            Bs[kr * LDB + c4 + 0] = wmma::__float_to_tf32(v.x);
            Bs[kr * LDB + c4 + 1] = wmma::__float_to_tf32(v.y);
            Bs[kr * LDB + c4 + 2] = wmma::__float_to_tf32(v.z);
            Bs[kr * LDB + c4 + 3] = wmma::__float_to_tf32(v.w);
        }
        __syncthreads();

#pragma unroll
        for (int kk = 0; kk < BK; kk += 8) {
            wmma::fragment<wmma::matrix_a, 16, 16, 8, wmma::precision::tf32, wmma::row_major> af[FM];
            wmma::fragment<wmma::matrix_b, 16, 16, 8, wmma::precision::tf32, wmma::row_major> bf[FN];
#pragma unroll
            for (int fm = 0; fm < FM; fm++)
                wmma::load_matrix_sync(af[fm], &As[(wm * WTM + fm * 16) * LDA + kk], LDA);
#pragma unroll
            for (int fn = 0; fn < FN; fn++)
                wmma::load_matrix_sync(bf[fn], &Bs[kk * LDB + wn * WTN + fn * 16], LDB);
#pragma unroll
            for (int fm = 0; fm < FM; fm++)
#pragma unroll
                for (int fn = 0; fn < FN; fn++)
                    wmma::mma_sync(acc[fm][fn], af[fm], bf[fn], acc[fm][fn]);
        }
        __syncthreads();
    }

#pragma unroll
    for (int fm = 0; fm < FM; fm++)
#pragma unroll
        for (int fn = 0; fn < FN; fn++)
            wmma::store_matrix_sync(
                &C[(size_t)(bm + wm * WTM + fm * 16) * N + bn + wn * WTN + fn * 16],
                acc[fm][fn], N, wmma::mem_row_major);
}

// ---------------- layer-1 aggregate (CSR gather) + self + bias + relu -------
__global__ __launch_bounds__(256)
void k_agg1(const int* __restrict__ rowptr, const int* __restrict__ csrc,
            const float* __restrict__ dinv, const float* __restrict__ h1,
            const float* __restrict__ b1, float* __restrict__ y) {
    int node = (blockIdx.x * blockDim.x + threadIdx.x) >> 5;
    if (node >= N_NODES) return;
    int lane = threadIdx.x & 31;
    int beg = __ldg(&rowptr[node]);
    int end = __ldg(&rowptr[node + 1]);
    float dd = __ldg(&dinv[node]);

    float4 a0 = {0, 0, 0, 0}, a1 = {0, 0, 0, 0}, a2 = {0, 0, 0, 0}, a3 = {0, 0, 0, 0};
    const float4* H = reinterpret_cast<const float4*>(h1);
    for (int j = beg; j < end; j++) {
        int s = __ldg(&csrc[j]);
        float nrm = dd * __ldg(&dinv[s]);
        const float4* hp = H + (size_t)s * 128;
        float4 v0 = __ldg(hp + lane);
        float4 v1 = __ldg(hp + lane + 32);
        float4 v2 = __ldg(hp + lane + 64);
        float4 v3 = __ldg(hp + lane + 96);
        a0.x += v0.x * nrm; a0.y += v0.y * nrm; a0.z += v0.z * nrm; a0.w += v0.w * nrm;
        a1.x += v1.x * nrm; a1.y += v1.y * nrm; a1.z += v1.z * nrm; a1.w += v1.w * nrm;
        a2.x += v2.x * nrm; a2.y += v2.y * nrm; a2.z += v2.z * nrm; a2.w += v2.w * nrm;
        a3.x += v3.x * nrm; a3.y += v3.y * nrm; a3.z += v3.z * nrm; a3.w += v3.w * nrm;
    }
    float w = dd * dd;
    const float4* hs = H + (size_t)node * 128;
    const float4* B4 = reinterpret_cast<const float4*>(b1);
    float4* Y = reinterpret_cast<float4*>(y) + (size_t)node * 128;
    float4 accs[4] = {a0, a1, a2, a3};
#pragma unroll
    for (int kchunk = 0; kchunk < 4; kchunk++) {
        int off = lane + kchunk * 32;
        float4 h = __ldg(hs + off);
        float4 b = __ldg(B4 + off);
        float4 r;
        r.x = fmaxf(accs[kchunk].x + h.x * w + b.x, 0.f);
        r.y = fmaxf(accs[kchunk].y + h.y * w + b.y, 0.f);
        r.z = fmaxf(accs[kchunk].z + h.z * w + b.z, 0.f);
        r.w = fmaxf(accs[kchunk].w + h.w * w + b.w, 0.f);
        Y[off] = r;
    }
}

// ---------------- layer-2 aggregate + self + bias + log_softmax -> out ------
__global__ __launch_bounds__(256)
void k_agg2(const int* __restrict__ rowptr, const int* __restrict__ csrc,
            const float* __restrict__ dinv, const float* __restrict__ h2,
            const float* __restrict__ b2, float* __restrict__ out) {
    int node = (blockIdx.x * blockDim.x + threadIdx.x) >> 5;
    if (node >= N_NODES) return;
    int lane = threadIdx.x & 31;
    int beg = __ldg(&rowptr[node]);
    int end = __ldg(&rowptr[node + 1]);
    float dd = __ldg(&dinv[node]);

    float2 acc = {0, 0};
    const float2* H2 = reinterpret_cast<const float2*>(h2);
    for (int j = beg; j < end; j++) {
        int s = __ldg(&csrc[j]);
        float nrm = dd * __ldg(&dinv[s]);
        float2 v = __ldg(H2 + (size_t)s * 32 + lane);
        acc.x += v.x * nrm;
        acc.y += v.y * nrm;
    }
    float w = dd * dd;
    float2 hv = __ldg(H2 + (size_t)node * 32 + lane);
    float2 bv = reinterpret_cast<const float2*>(b2)[lane];
    float v0 = acc.x + hv.x * w + bv.x;
    float v1 = acc.y + hv.y * w + bv.y;

    size_t base = (size_t)node * OUT_SIZE;
    out[base + 2 * lane] = v0;
    out[base + 2 * lane + 1] = v1;

    float m = fmaxf(v0, v1);
#pragma unroll
    for (int o = 16; o > 0; o >>= 1) m = fmaxf(m, __shfl_xor_sync(0xffffffffu, m, o));
    float s = expf(v0 - m) + expf(v1 - m);
#pragma unroll
    for (int o = 16; o > 0; o >>= 1) s += __shfl_xor_sync(0xffffffffu, s, o);
    float lse = m + logf(s);
    const size_t half = (size_t)N_NODES * OUT_SIZE;
    out[half + base + 2 * lane] = v0 - lse;
    out[half + base + 2 * lane + 1] = v1 - lse;
}

// ---------------- launch ----------------------------------------------------
extern "C" void kernel_launch(void* const* d_in, const int* in_sizes, int n_in,
                              void* d_out, int out_size) {
    const float* x  = (const float*)d_in[0];
    const int*   ei = (const int*)d_in[1];   // [2, E]: src row then dst row
    const float* W1 = (const float*)d_in[2];
    const float* b1 = (const float*)d_in[3];
    const float* W2 = (const float*)d_in[4];
    const float* b2 = (const float*)d_in[5];
    float* out = (float*)d_out;

    const int* src = ei;
    const int* dst = ei + N_EDGES;

    float *dinv, *h1, *y, *h2;
    int *cnt, *rowptr, *cursor, *csrc;
    cudaGetSymbolAddress((void**)&dinv,   g_dinv);
    cudaGetSymbolAddress((void**)&cnt,    g_cnt);
    cudaGetSymbolAddress((void**)&rowptr, g_rowptr);
    cudaGetSymbolAddress((void**)&cursor, g_cursor);
    cudaGetSymbolAddress((void**)&csrc,   g_csrc);
    cudaGetSymbolAddress((void**)&h1,     g_h1);
    cudaGetSymbolAddress((void**)&y,      g_y);
    cudaGetSymbolAddress((void**)&h2,     g_h2);

    // 1) histogram (cnt is zero: static init / re-zeroed by k_scan)
    k_hist<<<(N_EDGES + 255) / 256, 256>>>(dst, cnt);
    // 2) scan -> rowptr/cursor/dinv (+ re-zero cnt)
    k_scan<<<1, SCAN_T>>>(cnt, rowptr, cursor, dinv);
    // 3) fill CSR column indices
    k_fill<<<(N_EDGES + 255) / 256, 256>>>(src, dst, cursor, csrc);

    // 4) GEMM1: h1 = x @ W1   [10000,512]x[512,512]
    {
        dim3 grid((N_NODES + 127) / 128, H_SIZE / 64);
        k_wmma<128, 64, 32, 4, 2><<<grid, 256>>>(x, W1, h1, N_NODES, H_SIZE, IN_SIZE);
    }

    // 5) layer-1 aggregation + relu
    k_agg1<<<(N_NODES * 32 + 255) / 256, 256>>>(rowptr, csrc, dinv, h1, b1, y);

    // 6) GEMM2: h2 = y @ W2   [10000,512]x[512,64]  (profiled launch)
    {
        dim3 grid((N_NODES + 63) / 64, OUT_SIZE / 64);
        k_wmma<64, 64, 32, 2, 4><<<grid, 256>>>(y, W2, h2, N_NODES, OUT_SIZE, H_SIZE);
    }

    // 7) layer-2 aggregation + bias + log_softmax -> out
    k_agg2<<<(N_NODES * 32 + 255) / 256, 256>>>(rowptr, csrc, dinv, h2, b2, out);
}

// round 10
// speedup vs baseline: 1.1308x; 1.1227x over previous
#include <cuda_runtime.h>
#include <cuda_bf16.h>
#include <mma.h>
#include <cstdint>

using namespace nvcuda;

#define N_NODES 10000
#define N_EDGES 163840
#define IN_SIZE 512
#define H_SIZE 512
#define OUT_SIZE 64
#define M_PAD 10112   // padded row count (>= ceil(10000/128)*128)

// ---------------- scratch (device globals; no allocation allowed) ----------
// g_cnt starts zero (static zero-init); k_scan re-zeros it after consuming,
// so it is zero before k_hist on every graph replay.
__device__ float g_dinv[N_NODES];
__device__ int   g_cnt[N_NODES];
__device__ int   g_rowptr[N_NODES + 1];
__device__ int   g_cursor[N_NODES];
__device__ int   g_csrc[N_EDGES];
__device__ float g_h1[(size_t)M_PAD * H_SIZE];   // x@W1 (raw)
__device__ float g_y[(size_t)M_PAD * H_SIZE];    // relu(Â h1 + b1)
__device__ float g_h2[(size_t)M_PAD * OUT_SIZE]; // y@W2 (raw)

// ---------------- CSR build -------------------------------------------------
__global__ void k_hist(const int* __restrict__ dst, int* cnt) {
    int e = blockIdx.x * blockDim.x + threadIdx.x;
    if (e < N_EDGES) atomicAdd(&cnt[dst[e]], 1);
}

// single-block scan (warp-shuffle, 2 barriers) over 10000 counts.
// Produces rowptr (exclusive), cursor copy, dinv; re-zeros cnt for next replay.
#define SCAN_T 1024
#define SCAN_E 10
__global__ __launch_bounds__(SCAN_T)
void k_scan(int* cnt, int* rowptr, int* cursor, float* dinv) {
    __shared__ int wsum[32];
    const int t = threadIdx.x;
    const int lane = t & 31;
    const int wid = t >> 5;
    const int base = t * SCAN_E;

    int c[SCAN_E];
    int s = 0;
#pragma unroll
    for (int i = 0; i < SCAN_E; i++) {
        int idx = base + i;
        c[i] = (idx < N_NODES) ? cnt[idx] : 0;
        s += c[i];
    }
    int ws = s;
#pragma unroll
    for (int o = 1; o < 32; o <<= 1) {
        int v = __shfl_up_sync(0xffffffffu, ws, o);
        if (lane >= o) ws += v;
    }
    if (lane == 31) wsum[wid] = ws;
    __syncthreads();
    if (wid == 0) {
        int v = wsum[lane];
#pragma unroll
        for (int o = 1; o < 32; o <<= 1) {
            int u = __shfl_up_sync(0xffffffffu, v, o);
            if (lane >= o) v += u;
        }
        wsum[lane] = v;
    }
    __syncthreads();

    int warp_excl = (wid == 0) ? 0 : wsum[wid - 1];
    int run = warp_excl + ws - s;
#pragma unroll
    for (int i = 0; i < SCAN_E; i++) {
        int idx = base + i;
        if (idx < N_NODES) {
            rowptr[idx] = run;
            cursor[idx] = run;
            dinv[idx] = rsqrtf((float)(c[i] + 1));  // +1 self loop
            cnt[idx] = 0;                            // re-zero for next replay
            run += c[i];
        }
    }
    if (t == SCAN_T - 1) rowptr[N_NODES] = wsum[31];
}

__global__ void k_fill(const int* __restrict__ src, const int* __restrict__ dst,
                       int* cursor, int* csrc) {
    int e = blockIdx.x * blockDim.x + threadIdx.x;
    if (e >= N_EDGES) return;
    int d = dst[e];
    int pos = atomicAdd(&cursor[d], 1);
    csrc[pos] = src[e];
}

// ---------------- TF32 WMMA GEMM (sync loads, single buffer, occ>=3) --------
// fp32->tf32 RN conversion happens in the smem fill path.
// C rows are padded (stores unguarded); A rows >= M read as zero.
template <int BM, int BN, int BK, int WM, int WN>
__global__ __launch_bounds__(256, 3)
void k_wmma(const float* __restrict__ A, const float* __restrict__ B,
            float* __restrict__ C, int M, int N, int K) {
    constexpr int LDA = BK + 4;
    constexpr int LDB = BN + 4;
    constexpr int WTM = BM / WM;
    constexpr int WTN = BN / WN;
    constexpr int FM = WTM / 16;
    constexpr int FN = WTN / 16;
    __shared__ float As[BM * LDA];
    __shared__ float Bs[BK * LDB];

    const int tid = threadIdx.x;
    const int wid = tid >> 5;
    const int wm = wid % WM;
    const int wn = wid / WM;
    const int bm = blockIdx.x * BM;
    const int bn = blockIdx.y * BN;

    wmma::fragment<wmma::accumulator, 16, 16, 8, float> acc[FM][FN];
#pragma unroll
    for (int fm = 0; fm < FM; fm++)
#pragma unroll
        for (int fn = 0; fn < FN; fn++) wmma::fill_fragment(acc[fm][fn], 0.0f);

    constexpr int LA = (BM * BK) / (4 * 256);
    constexpr int LB = (BK * BN) / (4 * 256);

    for (int k0 = 0; k0 < K; k0 += BK) {
#pragma unroll
        for (int i = 0; i < LA; i++) {
            int idx = tid + i * 256;
            int row = idx / (BK / 4);
            int c4 = (idx % (BK / 4)) * 4;
            float4 v = make_float4(0.f, 0.f, 0.f, 0.f);
            if (bm + row < M)
                v = *reinterpret_cast<const float4*>(&A[(size_t)(bm + row) * K + k0 + c4]);
            As[row * LDA + c4 + 0] = wmma::__float_to_tf32(v.x);
            As[row * LDA + c4 + 1] = wmma::__float_to_tf32(v.y);
            As[row * LDA + c4 + 2] = wmma::__float_to_tf32(v.z);
            As[row * LDA + c4 + 3] = wmma::__float_to_tf32(v.w);
        }
#pragma unroll
        for (int i = 0; i < LB; i++) {
            int idx = tid + i * 256;
            int kr = idx / (BN / 4);
            int c4 = (idx % (BN / 4)) * 4;
            float4 v = *reinterpret_cast<const float4*>(&B[(size_t)(k0 + kr) * N + bn + c4]);
            Bs[kr * LDB + c4 + 0] = wmma::__float_to_tf32(v.x);
            Bs[kr * LDB + c4 + 1] = wmma::__float_to_tf32(v.y);
            Bs[kr * LDB + c4 + 2] = wmma::__float_to_tf32(v.z);
            Bs[kr * LDB + c4 + 3] = wmma::__float_to_tf32(v.w);
        }
        __syncthreads();

#pragma unroll
        for (int kk = 0; kk < BK; kk += 8) {
            wmma::fragment<wmma::matrix_a, 16, 16, 8, wmma::precision::tf32, wmma::row_major> af[FM];
            wmma::fragment<wmma::matrix_b, 16, 16, 8, wmma::precision::tf32, wmma::row_major> bf[FN];
#pragma unroll
            for (int fm = 0; fm < FM; fm++)
                wmma::load_matrix_sync(af[fm], &As[(wm * WTM + fm * 16) * LDA + kk], LDA);
#pragma unroll
            for (int fn = 0; fn < FN; fn++)
                wmma::load_matrix_sync(bf[fn], &Bs[kk * LDB + wn * WTN + fn * 16], LDB);
#pragma unroll
            for (int fm = 0; fm < FM; fm++)
#pragma unroll
                for (int fn = 0; fn < FN; fn++)
                    wmma::mma_sync(acc[fm][fn], af[fm], bf[fn], acc[fm][fn]);
        }
        __syncthreads();
    }

#pragma unroll
    for (int fm = 0; fm < FM; fm++)
#pragma unroll
        for (int fn = 0; fn < FN; fn++)
            wmma::store_matrix_sync(
                &C[(size_t)(bm + wm * WTM + fm * 16) * N + bn + wn * WTN + fn * 16],
                acc[fm][fn], N, wmma::mem_row_major);
}

// ---------------- layer-1 aggregate (CSR gather) + self + bias + relu -------
__global__ __launch_bounds__(256)
void k_agg1(const int* __restrict__ rowptr, const int* __restrict__ csrc,
            const float* __restrict__ dinv, const float* __restrict__ h1,
            const float* __restrict__ b1, float* __restrict__ y) {
    int node = (blockIdx.x * blockDim.x + threadIdx.x) >> 5;
    if (node >= N_NODES) return;
    int lane = threadIdx.x & 31;
    int beg = __ldg(&rowptr[node]);
    int end = __ldg(&rowptr[node + 1]);
    float dd = __ldg(&dinv[node]);

    float4 a0 = {0, 0, 0, 0}, a1 = {0, 0, 0, 0}, a2 = {0, 0, 0, 0}, a3 = {0, 0, 0, 0};
    const float4* H = reinterpret_cast<const float4*>(h1);
    for (int j = beg; j < end; j++) {
        int s = __ldg(&csrc[j]);
        float nrm = dd * __ldg(&dinv[s]);
        const float4* hp = H + (size_t)s * 128;
        float4 v0 = __ldg(hp + lane);
        float4 v1 = __ldg(hp + lane + 32);
        float4 v2 = __ldg(hp + lane + 64);
        float4 v3 = __ldg(hp + lane + 96);
        a0.x += v0.x * nrm; a0.y += v0.y * nrm; a0.z += v0.z * nrm; a0.w += v0.w * nrm;
        a1.x += v1.x * nrm; a1.y += v1.y * nrm; a1.z += v1.z * nrm; a1.w += v1.w * nrm;
        a2.x += v2.x * nrm; a2.y += v2.y * nrm; a2.z += v2.z * nrm; a2.w += v2.w * nrm;
        a3.x += v3.x * nrm; a3.y += v3.y * nrm; a3.z += v3.z * nrm; a3.w += v3.w * nrm;
    }
    float w = dd * dd;
    const float4* hs = H + (size_t)node * 128;
    const float4* B4 = reinterpret_cast<const float4*>(b1);
    float4* Y = reinterpret_cast<float4*>(y) + (size_t)node * 128;
    float4 accs[4] = {a0, a1, a2, a3};
#pragma unroll
    for (int kchunk = 0; kchunk < 4; kchunk++) {
        int off = lane + kchunk * 32;
        float4 h = __ldg(hs + off);
        float4 b = __ldg(B4 + off);
        float4 r;
        r.x = fmaxf(accs[kchunk].x + h.x * w + b.x, 0.f);
        r.y = fmaxf(accs[kchunk].y + h.y * w + b.y, 0.f);
        r.z = fmaxf(accs[kchunk].z + h.z * w + b.z, 0.f);
        r.w = fmaxf(accs[kchunk].w + h.w * w + b.w, 0.f);
        Y[off] = r;
    }
}

// ---------------- layer-2 aggregate + self + bias + log_softmax -> out ------
__global__ __launch_bounds__(256)
void k_agg2(const int* __restrict__ rowptr, const int* __restrict__ csrc,
            const float* __restrict__ dinv, const float* __restrict__ h2,
            const float* __restrict__ b2, float* __restrict__ out) {
    int node = (blockIdx.x * blockDim.x + threadIdx.x) >> 5;
    if (node >= N_NODES) return;
    int lane = threadIdx.x & 31;
    int beg = __ldg(&rowptr[node]);
    int end = __ldg(&rowptr[node + 1]);
    float dd = __ldg(&dinv[node]);

    float2 acc = {0, 0};
    const float2* H2 = reinterpret_cast<const float2*>(h2);
    for (int j = beg; j < end; j++) {
        int s = __ldg(&csrc[j]);
        float nrm = dd * __ldg(&dinv[s]);
        float2 v = __ldg(H2 + (size_t)s * 32 + lane);
        acc.x += v.x * nrm;
        acc.y += v.y * nrm;
    }
    float w = dd * dd;
    float2 hv = __ldg(H2 + (size_t)node * 32 + lane);
    float2 bv = reinterpret_cast<const float2*>(b2)[lane];
    float v0 = acc.x + hv.x * w + bv.x;
    float v1 = acc.y + hv.y * w + bv.y;

    size_t base = (size_t)node * OUT_SIZE;
    out[base + 2 * lane] = v0;
    out[base + 2 * lane + 1] = v1;

    float m = fmaxf(v0, v1);
#pragma unroll
    for (int o = 16; o > 0; o >>= 1) m = fmaxf(m, __shfl_xor_sync(0xffffffffu, m, o));
    float s = expf(v0 - m) + expf(v1 - m);
#pragma unroll
    for (int o = 16; o > 0; o >>= 1) s += __shfl_xor_sync(0xffffffffu, s, o);
    float lse = m + logf(s);
    const size_t half = (size_t)N_NODES * OUT_SIZE;
    out[half + base + 2 * lane] = v0 - lse;
    out[half + base + 2 * lane + 1] = v1 - lse;
}

// ---------------- launch ----------------------------------------------------
extern "C" void kernel_launch(void* const* d_in, const int* in_sizes, int n_in,
                              void* d_out, int out_size) {
    const float* x  = (const float*)d_in[0];
    const int*   ei = (const int*)d_in[1];   // [2, E]: src row then dst row
    const float* W1 = (const float*)d_in[2];
    const float* b1 = (const float*)d_in[3];
    const float* W2 = (const float*)d_in[4];
    const float* b2 = (const float*)d_in[5];
    float* out = (float*)d_out;

    const int* src = ei;
    const int* dst = ei + N_EDGES;

    float *dinv, *h1, *y, *h2;
    int *cnt, *rowptr, *cursor, *csrc;
    cudaGetSymbolAddress((void**)&dinv,   g_dinv);
    cudaGetSymbolAddress((void**)&cnt,    g_cnt);
    cudaGetSymbolAddress((void**)&rowptr, g_rowptr);
    cudaGetSymbolAddress((void**)&cursor, g_cursor);
    cudaGetSymbolAddress((void**)&csrc,   g_csrc);
    cudaGetSymbolAddress((void**)&h1,     g_h1);
    cudaGetSymbolAddress((void**)&y,      g_y);
    cudaGetSymbolAddress((void**)&h2,     g_h2);

    // Side stream + fork/join events (created per call, never destroyed:
    // destroying a capture-participating stream would invalidate the capture;
    // ~3 calls total -> negligible host-handle leak, zero device memory).
    cudaStream_t s2;
    cudaStreamCreateWithFlags(&s2, cudaStreamNonBlocking);
    cudaEvent_t evFork, evJoin;
    cudaEventCreateWithFlags(&evFork, cudaEventDisableTiming);
    cudaEventCreateWithFlags(&evJoin, cudaEventDisableTiming);

    // fork: CSR chain on s2, concurrent with GEMM1 on the main stream
    cudaEventRecord(evFork, 0);
    cudaStreamWaitEvent(s2, evFork, 0);

    k_hist<<<(N_EDGES + 255) / 256, 256, 0, s2>>>(dst, cnt);
    k_scan<<<1, SCAN_T, 0, s2>>>(cnt, rowptr, cursor, dinv);
    k_fill<<<(N_EDGES + 255) / 256, 256, 0, s2>>>(src, dst, cursor, csrc);
    cudaEventRecord(evJoin, s2);

    // GEMM1 on main stream: h1 = x @ W1   [10000,512]x[512,512]
    {
        dim3 grid((N_NODES + 127) / 128, H_SIZE / 64);
        k_wmma<128, 64, 32, 4, 2><<<grid, 256>>>(x, W1, h1, N_NODES, H_SIZE, IN_SIZE);
    }

    // join: aggregation needs both GEMM1 (main) and CSR (s2)
    cudaStreamWaitEvent(0, evJoin, 0);

    // layer-1 aggregation + relu
    k_agg1<<<(N_NODES * 32 + 255) / 256, 256>>>(rowptr, csrc, dinv, h1, b1, y);

    // GEMM2: h2 = y @ W2   [10000,512]x[512,64]
    {
        dim3 grid((N_NODES + 63) / 64, OUT_SIZE / 64);
        k_wmma<64, 64, 32, 2, 4><<<grid, 256>>>(y, W2, h2, N_NODES, OUT_SIZE, H_SIZE);
    }

    // layer-2 aggregation + bias + log_softmax -> out
    k_agg2<<<(N_NODES * 32 + 255) / 256, 256>>>(rowptr, csrc, dinv, h2, b2, out);
}